// round 10
// baseline (speedup 1.0000x reference)
#include <cuda_runtime.h>

#define BB 32
#define TT 2048
#define DD 1024
#define RPW 8    // rows per warp (contiguous run)
#define WPB 8    // warps per block

// Device scratch (no allocation allowed in kernel_launch)
__device__ float g_exp[BB * TT];   // unnormalized exp(e) per active row
__device__ float g_ctx[BB * DD];   // unnormalized context accumulators

__device__ __forceinline__ float fast_tanh(float x) {
    float y;
    asm("tanh.approx.f32 %0, %1;" : "=f"(y) : "f"(x));
    return y;
}

// ---------------------------------------------------------------------------
// Kernel 0: zero the context accumulators (needed every call; graph-replayed).
// ---------------------------------------------------------------------------
__global__ void zero_kernel()
{
    g_ctx[blockIdx.x * 256 + threadIdx.x] = 0.0f;   // grid = BB*DD/256 = 128
}

// ---------------------------------------------------------------------------
// Kernel 1 (fused): for each active row t of batch b:
//   e_t   = sum_d v[d] * tanh(keys[b,t,d] + query[b,d] + wf[b,t,d])
//   wexp  = exp(e_t)              (no max subtraction: |e| <= ~27, fp32-safe)
//   acc  += wexp * value[b,t,:]   (register accumulator, 32 floats/lane)
// Warp-per-row-run: each warp owns RPW consecutive rows, flushes acc once via
// atomicAdd. Single pass over keys+wf+value -> one streaming kernel.
// ---------------------------------------------------------------------------
__global__ void __launch_bounds__(256) fused_kernel(
    const float* __restrict__ keys,
    const float* __restrict__ query,
    const float* __restrict__ wf,
    const float* __restrict__ v,
    const float* __restrict__ value,
    const int* __restrict__ lens)
{
    const int b    = blockIdx.y;
    const int len  = __ldg(lens + b);
    const int warp = threadIdx.x >> 5;
    const int lane = threadIdx.x & 31;
    const int t0   = (blockIdx.x * WPB + warp) * RPW;
    if (t0 >= len) return;
    const int tend = min(t0 + RPW, len);

    const float4* q4 = reinterpret_cast<const float4*>(query + (size_t)b * DD);
    const float4* v4 = reinterpret_cast<const float4*>(v);

    float4 acc[8];
    #pragma unroll
    for (int j = 0; j < 8; ++j) acc[j] = make_float4(0.f, 0.f, 0.f, 0.f);

    for (int t = t0; t < tend; ++t) {
        const size_t row = ((size_t)b * TT + t) * DD;
        const float4* k4  = reinterpret_cast<const float4*>(keys  + row);
        const float4* f4  = reinterpret_cast<const float4*>(wf    + row);
        const float4* vl4 = reinterpret_cast<const float4*>(value + row);

        float s = 0.0f;
        #pragma unroll
        for (int j = 0; j < 8; ++j) {
            const int idx = lane + 32 * j;
            float4 kk = k4[idx];
            float4 ff = f4[idx];
            float4 qq = __ldg(q4 + idx);
            float4 vv = __ldg(v4 + idx);
            s += vv.x * fast_tanh(kk.x + qq.x + ff.x)
               + vv.y * fast_tanh(kk.y + qq.y + ff.y)
               + vv.z * fast_tanh(kk.z + qq.z + ff.z)
               + vv.w * fast_tanh(kk.w + qq.w + ff.w);
        }
        #pragma unroll
        for (int o = 16; o; o >>= 1) s += __shfl_xor_sync(0xffffffffu, s, o);

        const float wexp = __expf(s);          // all lanes hold full sum
        if (lane == 0) g_exp[b * TT + t] = wexp;

        #pragma unroll
        for (int j = 0; j < 8; ++j) {
            const int idx = lane + 32 * j;
            float4 vv = __ldcs(vl4 + idx);
            acc[j].x += wexp * vv.x;
            acc[j].y += wexp * vv.y;
            acc[j].z += wexp * vv.z;
            acc[j].w += wexp * vv.w;
        }
    }

    float* ctx = g_ctx + (size_t)b * DD;
    #pragma unroll
    for (int j = 0; j < 8; ++j) {
        const int idx = (lane + 32 * j) * 4;
        atomicAdd(ctx + idx + 0, acc[j].x);
        atomicAdd(ctx + idx + 1, acc[j].y);
        atomicAdd(ctx + idx + 2, acc[j].z);
        atomicAdd(ctx + idx + 3, acc[j].w);
    }
}

// ---------------------------------------------------------------------------
// Kernel 2 (finalize): per batch, S = sum of exps; write normalized weights
// (0 for masked t) and normalized context. All inputs L2-resident.
// ---------------------------------------------------------------------------
__global__ void __launch_bounds__(256) finalize_kernel(
    const int* __restrict__ lens,
    float* __restrict__ out)
{
    const int b = blockIdx.x;
    const int len = __ldg(lens + b);
    const float* e = g_exp + b * TT;
    float* wout = out + (size_t)BB * DD + (size_t)b * TT;  // weights region
    float* cout = out + (size_t)b * DD;                    // context region

    const int tid = threadIdx.x;
    __shared__ float red[8];
    __shared__ float s_sum;

    float s = 0.f;
    for (int t = tid; t < len; t += 256) s += e[t];
    #pragma unroll
    for (int o = 16; o; o >>= 1) s += __shfl_xor_sync(0xffffffffu, s, o);
    if ((tid & 31) == 0) red[tid >> 5] = s;
    __syncthreads();
    if (tid == 0) {
        float ss = red[0];
        #pragma unroll
        for (int j = 1; j < 8; j++) ss += red[j];
        s_sum = ss;
    }
    __syncthreads();
    const float inv = 1.0f / s_sum;

    for (int t = tid; t < TT; t += 256)
        wout[t] = (t < len) ? e[t] * inv : 0.0f;

    const float* ctx = g_ctx + (size_t)b * DD;
    for (int i = tid; i < DD; i += 256)
        cout[i] = ctx[i] * inv;
}

// ---------------------------------------------------------------------------
extern "C" void kernel_launch(void* const* d_in, const int* in_sizes, int n_in,
                              void* d_out, int out_size)
{
    const float* keys  = (const float*)d_in[0];
    const float* value = (const float*)d_in[1];
    const float* query = (const float*)d_in[2];
    const float* wf    = (const float*)d_in[3];
    const float* v     = (const float*)d_in[4];
    const int*   lens  = (const int*)d_in[5];
    float* out = (float*)d_out;

    zero_kernel<<<BB * DD / 256, 256>>>();
    fused_kernel<<<dim3(TT / (RPW * WPB), BB), 256>>>(keys, query, wf, v, value, lens);
    finalize_kernel<<<BB, 256>>>(lens, out);
}

// round 11
// speedup vs baseline: 1.5966x; 1.5966x over previous
#include <cuda_runtime.h>

#define BB 32
#define TT 2048
#define DD 1024
#define CHUNK 64   // rows per block (8 warps x 8 rows)

// Device scratch (no allocation allowed in kernel_launch).
// g_ctx is zero-initialized at module load; finalize_kernel re-zeroes it after
// consuming, so every graph replay starts from zeros. Deterministic.
__device__ float g_exp[BB * TT];
__device__ float g_ctx[BB * DD];

__device__ __forceinline__ float fast_tanh(float x) {
    float y;
    asm("tanh.approx.f32 %0, %1;" : "=f"(y) : "f"(x));
    return y;
}

// ---------------------------------------------------------------------------
// Fused kernel: one block owns a 64-row chunk of batch b.
// Phase 1 (R9 energy form): warp-per-row, e_t = v . tanh(k+q+wf),
//   wexp = exp(e_t)  (no max subtraction: |e| bounded by sum|v| ~ 27, fp32-safe)
//   -> smem + g_exp.
// Phase 2 (R9 context form): each thread owns one float4 of D, accumulates
//   sum_t wexp_t * value[t], single atomic flush into g_ctx.
// No accumulator is live during the load-heavy phase -> low register pressure.
// Masked chunks exit before any barrier.
// ---------------------------------------------------------------------------
__global__ void __launch_bounds__(256) fused_kernel(
    const float* __restrict__ keys,
    const float* __restrict__ query,
    const float* __restrict__ wf,
    const float* __restrict__ v,
    const float* __restrict__ value,
    const int* __restrict__ lens)
{
    const int b   = blockIdx.y;
    const int len = __ldg(lens + b);
    const int t0  = blockIdx.x * CHUNK;
    if (t0 >= len) return;
    const int tend = min(t0 + CHUNK, len);

    __shared__ float s_exp[CHUNK];

    const int warp = threadIdx.x >> 5;
    const int lane = threadIdx.x & 31;
    const float4* q4 = reinterpret_cast<const float4*>(query + (size_t)b * DD);
    const float4* v4 = reinterpret_cast<const float4*>(v);

    // ---------- Phase 1: energies -> exp ----------
    #pragma unroll
    for (int k = 0; k < CHUNK / 8; ++k) {
        const int t = t0 + warp + 8 * k;       // stride-8: warp w does rows w, w+8, ...
        if (t < tend) {
            const size_t row = ((size_t)b * TT + t) * DD;
            const float4* k4 = reinterpret_cast<const float4*>(keys + row);
            const float4* f4 = reinterpret_cast<const float4*>(wf + row);

            float s = 0.0f;
            #pragma unroll
            for (int j = 0; j < 8; ++j) {
                const int idx = lane + 32 * j;
                float4 kk = k4[idx];
                float4 ff = f4[idx];
                float4 qq = __ldg(q4 + idx);
                float4 vv = __ldg(v4 + idx);
                s += vv.x * fast_tanh(kk.x + qq.x + ff.x)
                   + vv.y * fast_tanh(kk.y + qq.y + ff.y)
                   + vv.z * fast_tanh(kk.z + qq.z + ff.z)
                   + vv.w * fast_tanh(kk.w + qq.w + ff.w);
            }
            #pragma unroll
            for (int o = 16; o; o >>= 1) s += __shfl_xor_sync(0xffffffffu, s, o);

            if (lane == 0) {
                const float wexp = __expf(s);
                s_exp[t - t0] = wexp;
                g_exp[b * TT + t] = wexp;
            }
        }
    }
    __syncthreads();

    // ---------- Phase 2: weighted value accumulation ----------
    const int i = threadIdx.x;                 // one float4 of D per thread
    float4 acc = make_float4(0.f, 0.f, 0.f, 0.f);
    const float4* vb = reinterpret_cast<const float4*>(value)
                     + ((size_t)b * TT + t0) * (DD / 4);

    #pragma unroll 8
    for (int t = t0; t < tend; ++t) {
        const float w = s_exp[t - t0];
        float4 vv = __ldcs(vb + i);
        acc.x += w * vv.x;
        acc.y += w * vv.y;
        acc.z += w * vv.z;
        acc.w += w * vv.w;
        vb += DD / 4;
    }

    float* ctx = g_ctx + (size_t)b * DD + i * 4;
    atomicAdd(ctx + 0, acc.x);
    atomicAdd(ctx + 1, acc.y);
    atomicAdd(ctx + 2, acc.z);
    atomicAdd(ctx + 3, acc.w);
}

// ---------------------------------------------------------------------------
// Finalize: per batch, S = sum of exps; write normalized weights (0 for
// masked t) and normalized context; re-zero g_ctx for the next graph replay.
// All inputs L2-resident.
// ---------------------------------------------------------------------------
__global__ void __launch_bounds__(256) finalize_kernel(
    const int* __restrict__ lens,
    float* __restrict__ out)
{
    const int b = blockIdx.x;
    const int len = __ldg(lens + b);
    const float* e = g_exp + b * TT;
    float* wout = out + (size_t)BB * DD + (size_t)b * TT;  // weights region
    float* cout = out + (size_t)b * DD;                    // context region

    const int tid = threadIdx.x;
    __shared__ float red[8];
    __shared__ float s_sum;

    float s = 0.f;
    for (int t = tid; t < len; t += 256) s += e[t];
    #pragma unroll
    for (int o = 16; o; o >>= 1) s += __shfl_xor_sync(0xffffffffu, s, o);
    if ((tid & 31) == 0) red[tid >> 5] = s;
    __syncthreads();
    if (tid == 0) {
        float ss = red[0];
        #pragma unroll
        for (int j = 1; j < 8; j++) ss += red[j];
        s_sum = ss;
    }
    __syncthreads();
    const float inv = 1.0f / s_sum;

    for (int t = tid; t < TT; t += 256)
        wout[t] = (t < len) ? e[t] * inv : 0.0f;

    float* gctx = g_ctx + (size_t)b * DD;
    for (int i = tid; i < DD; i += 256) {
        cout[i] = gctx[i] * inv;
        gctx[i] = 0.0f;                  // restore invariant for next replay
    }
}

// ---------------------------------------------------------------------------
extern "C" void kernel_launch(void* const* d_in, const int* in_sizes, int n_in,
                              void* d_out, int out_size)
{
    const float* keys  = (const float*)d_in[0];
    const float* value = (const float*)d_in[1];
    const float* query = (const float*)d_in[2];
    const float* wf    = (const float*)d_in[3];
    const float* v     = (const float*)d_in[4];
    const int*   lens  = (const int*)d_in[5];
    float* out = (float*)d_out;

    fused_kernel<<<dim3(TT / CHUNK, BB), 256>>>(keys, query, wf, v, value, lens);
    finalize_kernel<<<BB, 256>>>(lens, out);
}